// round 12
// baseline (speedup 1.0000x reference)
#include <cuda_runtime.h>
#include <cuda.h>
#include <cuda_bf16.h>
#include <math.h>
#include <stdint.h>

#define M_TOTAL 25088   // 128*14*14
#define K_DIM   512
#define N_DIM   2048
#define KX      1024    // interleaved: 16 chunks of [hi(32)|lo(32)]

#define BM 128
#define BN 64
#define STAGES 3
#define NT 16                        // 16 chunks of K=32 (hi+lo together)
#define A_TILE_BYTES (BM * 128)      // 16384
#define B_TILE_BYTES (BN * 128)      // 8192
#define STAGE_BYTES (A_TILE_BYTES + B_TILE_BYTES)  // 24576
#define SMEM_DYN (STAGES * STAGE_BYTES + 1024)

#define TOTAL_ROWS (M_TOTAL + N_DIM) // 27136
#define ROWS_PER_BLK 4               // 4 warps per 128-thread block (convert)

// bf16 hi/lo scratch (allocation-free device globals)
__device__ __nv_bfloat16 g_A[(size_t)M_TOTAL * KX];
__device__ __nv_bfloat16 g_B[(size_t)N_DIM * KX];

// ---------------------------------------------------------------------------
// PTX helpers (sm_90-baseline features only)
// ---------------------------------------------------------------------------
__device__ __forceinline__ uint32_t smem_u32(const void* p) {
    uint32_t a;
    asm("{ .reg .u64 t; cvta.to.shared.u64 t, %1; cvt.u32.u64 %0, t; }" : "=r"(a) : "l"(p));
    return a;
}

#define MBARRIER_INIT(addr, cnt) \
    asm volatile("mbarrier.init.shared.b64 [%0], %1;" :: "r"(addr), "r"(cnt) : "memory")

#define MBARRIER_EXPECT_TX(addr, bytes) \
    asm volatile("mbarrier.arrive.expect_tx.shared.b64 _, [%0], %1;" :: "r"(addr), "r"(bytes) : "memory")

#define MBARRIER_WAIT_PARITY(addr, parity) do {                                   \
    uint32_t _mbar = (uint32_t)(addr);                                            \
    uint32_t _par  = (uint32_t)(parity);                                          \
    uint32_t _done;                                                               \
    asm volatile(                                                                 \
        "{\n\t.reg .pred p;\n\t"                                                  \
        "mbarrier.try_wait.parity.acquire.cta.shared::cta.b64 p, [%1], %2;\n\t"   \
        "selp.b32 %0, 1, 0, p;\n\t}"                                              \
        : "=r"(_done) : "r"(_mbar), "r"(_par) : "memory");                        \
    if (!_done) {                                                                 \
        asm volatile(                                                             \
            "{\n\t.reg .pred P1;\n\t"                                             \
            "WAIT_LOOP_%=:\n\t"                                                   \
            "mbarrier.try_wait.parity.acquire.cta.shared::cta.b64 P1, [%0], %1, 0x989680;\n\t" \
            "@P1 bra.uni WAIT_DONE_%=;\n\t"                                       \
            "bra.uni WAIT_LOOP_%=;\n\t"                                           \
            "WAIT_DONE_%=:\n\t}"                                                  \
            :: "r"(_mbar), "r"(_par) : "memory");                                 \
    }                                                                             \
} while (0)

#define TMA_LOAD_3D(smem_addr, tmap, cx, cy, cz, mbar)                            \
    asm volatile(                                                                 \
        "cp.async.bulk.tensor.3d.shared::cta.global.tile.mbarrier::complete_tx::bytes " \
        "[%0], [%1, {%2, %3, %4}], [%5];"                                         \
        :: "r"((uint32_t)(smem_addr)), "l"(tmap), "r"((int32_t)(cx)),             \
           "r"((int32_t)(cy)), "r"((int32_t)(cz)), "r"((uint32_t)(mbar))          \
        : "memory")

#define LDSM_X4(r, addr) \
    asm volatile("ldmatrix.sync.aligned.m8n8.x4.shared.b16 {%0,%1,%2,%3}, [%4];" \
        : "=r"((r)[0]), "=r"((r)[1]), "=r"((r)[2]), "=r"((r)[3]) : "r"(addr))

__device__ __forceinline__ void mma16816(float* d, const uint32_t* a, const uint32_t* b) {
    asm volatile(
        "mma.sync.aligned.m16n8k16.row.col.f32.bf16.bf16.f32 "
        "{%0,%1,%2,%3}, {%4,%5,%6,%7}, {%8,%9}, {%0,%1,%2,%3};"
        : "+f"(d[0]), "+f"(d[1]), "+f"(d[2]), "+f"(d[3])
        : "r"(a[0]), "r"(a[1]), "r"(a[2]), "r"(a[3]), "r"(b[0]), "r"(b[1]));
}

__device__ __forceinline__ void split_bf16(float v, __nv_bfloat16& hi, __nv_bfloat16& lo) {
    hi = __float2bfloat16(v);
    lo = __float2bfloat16(v - __bfloat162float(hi));
}

// ---------------------------------------------------------------------------
// Kernel 1: warp-per-row convert, barrier-free (R11 winner, unchanged).
// ---------------------------------------------------------------------------
__global__ void __launch_bounds__(128) convert_kernel(
    const float* __restrict__ x,
    const float* __restrict__ gamma,
    const float* __restrict__ beta,
    const float* __restrict__ W)
{
    const int warp = threadIdx.x >> 5;
    const int lane = threadIdx.x & 31;
    const int row  = blockIdx.x * ROWS_PER_BLK + warp;

    if (row < M_TOTAL) {
        const float4* xr = reinterpret_cast<const float4*>(x + (size_t)row * K_DIM);
        float4 v[4];
        #pragma unroll
        for (int p = 0; p < 4; p++)
            v[p] = xr[p * 32 + lane];

        float s = 0.0f, sq = 0.0f;
        #pragma unroll
        for (int p = 0; p < 4; p++) {
            s  += v[p].x + v[p].y + v[p].z + v[p].w;
            sq += fmaf(v[p].x, v[p].x, fmaf(v[p].y, v[p].y,
                  fmaf(v[p].z, v[p].z, v[p].w * v[p].w)));
        }
        #pragma unroll
        for (int o = 16; o > 0; o >>= 1) {
            s  += __shfl_xor_sync(0xffffffff, s,  o);
            sq += __shfl_xor_sync(0xffffffff, sq, o);
        }
        const float mean = s * (1.0f / K_DIM);
        const float var  = sq * (1.0f / K_DIM) - mean * mean;
        const float rstd = rsqrtf(var + 1e-6f);

        const float4* gm = reinterpret_cast<const float4*>(gamma);
        const float4* bt = reinterpret_cast<const float4*>(beta);

        #pragma unroll
        for (int p = 0; p < 4; p++) {
            float4 g  = gm[p * 32 + lane];
            float4 be = bt[p * 32 + lane];
            float xn0 = (v[p].x - mean) * rstd * g.x + be.x;
            float xn1 = (v[p].y - mean) * rstd * g.y + be.y;
            float xn2 = (v[p].z - mean) * rstd * g.z + be.z;
            float xn3 = (v[p].w - mean) * rstd * g.w + be.w;

            __nv_bfloat16 h0, h1, h2, h3, l0, l1, l2, l3;
            split_bf16(xn0, h0, l0); split_bf16(xn1, h1, l1);
            split_bf16(xn2, h2, l2); split_bf16(xn3, h3, l3);

            const int j0 = (p * 32 + lane) * 4;
            const int c  = j0 >> 5;
            const int w  = j0 & 31;
            __nv_bfloat16* base = g_A + (size_t)row * KX + c * 64 + w;
            __nv_bfloat162* hd = reinterpret_cast<__nv_bfloat162*>(base);
            __nv_bfloat162* ld = reinterpret_cast<__nv_bfloat162*>(base + 32);
            hd[0] = __nv_bfloat162(h0, h1); hd[1] = __nv_bfloat162(h2, h3);
            ld[0] = __nv_bfloat162(l0, l1); ld[1] = __nv_bfloat162(l2, l3);
        }
    } else {
        const int wrow = row - M_TOTAL;
        const float4* wr = reinterpret_cast<const float4*>(W + (size_t)wrow * K_DIM);
        #pragma unroll
        for (int p = 0; p < 4; p++) {
            float4 v = wr[p * 32 + lane];
            __nv_bfloat16 h0, h1, h2, h3, l0, l1, l2, l3;
            split_bf16(v.x, h0, l0); split_bf16(v.y, h1, l1);
            split_bf16(v.z, h2, l2); split_bf16(v.w, h3, l3);

            const int j0 = (p * 32 + lane) * 4;
            const int c  = j0 >> 5;
            const int w  = j0 & 31;
            __nv_bfloat16* base = g_B + (size_t)wrow * KX + c * 64 + w;
            __nv_bfloat162* hd = reinterpret_cast<__nv_bfloat162*>(base);
            __nv_bfloat162* ld = reinterpret_cast<__nv_bfloat162*>(base + 32);
            hd[0] = __nv_bfloat162(h0, h1); hd[1] = __nv_bfloat162(h2, h3);
            ld[0] = __nv_bfloat162(l0, l1); ld[1] = __nv_bfloat162(l2, l3);
        }
    }
}

// ---------------------------------------------------------------------------
// Kernel 2: TMA-pipelined HMMA GEMM, 128x64 CTA tile, 4 warps, 3 CTAs/SM.
// Inner loop instruction-identical to the R4/R11 winner (warp tile 64x32).
// ---------------------------------------------------------------------------
__device__ __forceinline__ void issue_tile_load(
    int kt, int s, uint32_t tiles_base, uint32_t mbar,
    const CUtensorMap* mapA, const CUtensorMap* mapB, int bm, int bn)
{
    const uint32_t a_dst = tiles_base + s * STAGE_BYTES;
    const uint32_t b_dst = a_dst + A_TILE_BYTES;
    MBARRIER_EXPECT_TX(mbar, STAGE_BYTES);
    TMA_LOAD_3D(a_dst, mapA, kt * 64, bm, 0, mbar);   // box 64x128
    TMA_LOAD_3D(b_dst, mapB, kt * 64, bn, 0, mbar);   // box 64x64
}

__global__ void __launch_bounds__(128, 3) gemm_kernel(
    const __grid_constant__ CUtensorMap tma_a,
    const __grid_constant__ CUtensorMap tma_b,
    const float* __restrict__ bias,
    float* __restrict__ out)
{
    extern __shared__ char dynsmem[];
    __shared__ __align__(8) uint64_t mbar_full[STAGES];

    const int tid  = threadIdx.x;
    const int wid  = tid >> 5;
    const int lane = tid & 31;
    const int bm = blockIdx.y * BM;
    const int bn = blockIdx.x * BN;

    const int wm = (wid >> 1) * 64;   // 2 warps along M: 0, 64
    const int wn = (wid & 1) * 32;    // 2 warps along N: 0, 32

    const uint32_t tiles_base = (smem_u32(dynsmem) + 1023u) & ~1023u;

    if (tid == 0) {
        #pragma unroll
        for (int s = 0; s < STAGES; s++)
            MBARRIER_INIT(smem_u32(&mbar_full[s]), 1);
    }
    __syncthreads();

    if (tid == 0) {
        #pragma unroll
        for (int s = 0; s < STAGES; s++)
            issue_tile_load(s, s, tiles_base, smem_u32(&mbar_full[s]), &tma_a, &tma_b, bm, bn);
    }

    // --- per-lane ldmatrix address components (SW128 swizzle, 128B rows) ---
    const int a_row = wm + ((lane >> 3) & 1) * 8 + (lane & 7);
    const uint32_t a_row_off = (uint32_t)a_row * 128u;
    const uint32_t a_xor = (uint32_t)(a_row & 7) * 16u;
    const uint32_t a_kb = (uint32_t)(lane >> 4) * 16u;
    const int b_row = wn + (lane >> 4) * 8 + (lane & 7);
    const uint32_t b_row_off = (uint32_t)b_row * 128u;
    const uint32_t b_xor = (uint32_t)(b_row & 7) * 16u;
    const uint32_t b_kb = (uint32_t)((lane >> 3) & 1) * 16u;

    float acc[4][4][4];
    #pragma unroll
    for (int i = 0; i < 4; i++)
        #pragma unroll
        for (int j = 0; j < 4; j++)
            #pragma unroll
            for (int q = 0; q < 4; q++) acc[i][j][q] = 0.0f;

    for (int kt = 0; kt < NT; kt++) {
        const int s = kt % STAGES;
        const int par = (kt / STAGES) & 1;
        MBARRIER_WAIT_PARITY(smem_u32(&mbar_full[s]), par);

        const uint32_t a_base = tiles_base + s * STAGE_BYTES + a_row_off;
        const uint32_t b_base = tiles_base + s * STAGE_BYTES + A_TILE_BYTES + b_row_off;

        // within a 128B row: hi bytes [0,64), lo bytes [64,128); ks picks 32B
        #pragma unroll
        for (int ks = 0; ks < 2; ks++) {
            const uint32_t akh = (uint32_t)ks * 32u + a_kb;          // a_hi
            const uint32_t akl = akh + 64u;                          // a_lo
            const uint32_t bkh = (uint32_t)ks * 32u + b_kb;          // b_hi
            const uint32_t bkl = bkh + 64u;                          // b_lo

            uint32_t ah[4][4], bh[2][4], bl[2][4];
            #pragma unroll
            for (int mt = 0; mt < 4; mt++)
                LDSM_X4(ah[mt], a_base + (uint32_t)mt * 2048u + (akh ^ a_xor));
            #pragma unroll
            for (int np = 0; np < 2; np++) {
                LDSM_X4(bh[np], b_base + (uint32_t)np * 2048u + (bkh ^ b_xor));
                LDSM_X4(bl[np], b_base + (uint32_t)np * 2048u + (bkl ^ b_xor));
            }

            if (ks == 1) {
                uint32_t al[4][4];
                #pragma unroll
                for (int mt = 0; mt < 4; mt++)
                    LDSM_X4(al[mt], a_base + (uint32_t)mt * 2048u + (akl ^ a_xor));

                __syncthreads();   // all LDSMs of stage s done -> refill while MMAs run
                if (tid == 0 && kt + STAGES < NT)
                    issue_tile_load(kt + STAGES, s, tiles_base, smem_u32(&mbar_full[s]),
                                    &tma_a, &tma_b, bm, bn);

                #pragma unroll
                for (int mt = 0; mt < 4; mt++)
                    #pragma unroll
                    for (int nt = 0; nt < 4; nt++)
                        mma16816(acc[mt][nt], ah[mt], &bh[nt >> 1][(nt & 1) * 2]);
                #pragma unroll
                for (int mt = 0; mt < 4; mt++)
                    #pragma unroll
                    for (int nt = 0; nt < 4; nt++)
                        mma16816(acc[mt][nt], ah[mt], &bl[nt >> 1][(nt & 1) * 2]);
                #pragma unroll
                for (int mt = 0; mt < 4; mt++)
                    #pragma unroll
                    for (int nt = 0; nt < 4; nt++)
                        mma16816(acc[mt][nt], al[mt], &bh[nt >> 1][(nt & 1) * 2]);
            } else {
                uint32_t al[4][4];
                #pragma unroll
                for (int mt = 0; mt < 4; mt++)
                    LDSM_X4(al[mt], a_base + (uint32_t)mt * 2048u + (akl ^ a_xor));
                #pragma unroll
                for (int mt = 0; mt < 4; mt++)
                    #pragma unroll
                    for (int nt = 0; nt < 4; nt++)
                        mma16816(acc[mt][nt], ah[mt], &bh[nt >> 1][(nt & 1) * 2]);
                #pragma unroll
                for (int mt = 0; mt < 4; mt++)
                    #pragma unroll
                    for (int nt = 0; nt < 4; nt++)
                        mma16816(acc[mt][nt], ah[mt], &bl[nt >> 1][(nt & 1) * 2]);
                #pragma unroll
                for (int mt = 0; mt < 4; mt++)
                    #pragma unroll
                    for (int nt = 0; nt < 4; nt++)
                        mma16816(acc[mt][nt], al[mt], &bh[nt >> 1][(nt & 1) * 2]);
            }
        }
    }

    // --- epilogue: bias + exact GELU, float2 stores ---
    const int gr = lane >> 2;
    const int gc = (lane & 3) * 2;
    #pragma unroll
    for (int nt = 0; nt < 4; nt++) {
        const int n = bn + wn + nt * 8 + gc;
        const float2 b2 = __ldg(reinterpret_cast<const float2*>(bias + n));
        #pragma unroll
        for (int mt = 0; mt < 4; mt++) {
            const int m0 = bm + wm + mt * 16 + gr;
            float v0 = acc[mt][nt][0] + b2.x;
            float v1 = acc[mt][nt][1] + b2.y;
            float v2 = acc[mt][nt][2] + b2.x;
            float v3 = acc[mt][nt][3] + b2.y;
            float2 o0, o1;
            o0.x = 0.5f * v0 * (1.0f + erff(v0 * 0.70710678118654752f));
            o0.y = 0.5f * v1 * (1.0f + erff(v1 * 0.70710678118654752f));
            o1.x = 0.5f * v2 * (1.0f + erff(v2 * 0.70710678118654752f));
            o1.y = 0.5f * v3 * (1.0f + erff(v3 * 0.70710678118654752f));
            *reinterpret_cast<float2*>(out + (size_t)m0 * N_DIM + n) = o0;
            *reinterpret_cast<float2*>(out + (size_t)(m0 + 8) * N_DIM + n) = o1;
        }
    }
}

// ---------------------------------------------------------------------------
// Host side
// ---------------------------------------------------------------------------
typedef CUresult (*EncodeFn)(CUtensorMap*, CUtensorMapDataType, cuuint32_t, void*,
                             const cuuint64_t*, const cuuint64_t*, const cuuint32_t*,
                             const cuuint32_t*, CUtensorMapInterleave, CUtensorMapSwizzle,
                             CUtensorMapL2promotion, CUtensorMapFloatOOBfill);

static void encode_map(EncodeFn enc, CUtensorMap* map, void* base, uint64_t rows,
                       uint32_t box_rows) {
    uint64_t dims[3]    = {KX, rows, 1};
    uint64_t strides[2] = {KX * sizeof(__nv_bfloat16), rows * KX * sizeof(__nv_bfloat16)};
    uint32_t box[3]     = {64, box_rows, 1};
    uint32_t estr[3]    = {1, 1, 1};
    enc(map, CU_TENSOR_MAP_DATA_TYPE_BFLOAT16, 3, base, dims, strides, box, estr,
        CU_TENSOR_MAP_INTERLEAVE_NONE, CU_TENSOR_MAP_SWIZZLE_128B,
        CU_TENSOR_MAP_L2_PROMOTION_L2_128B, CU_TENSOR_MAP_FLOAT_OOB_FILL_NONE);
}

extern "C" void kernel_launch(void* const* d_in, const int* in_sizes, int n_in,
                              void* d_out, int out_size) {
    const float* x     = (const float*)d_in[0];
    const float* gamma = (const float*)d_in[1];
    const float* beta  = (const float*)d_in[2];
    const float* W     = (const float*)d_in[3];
    const float* b     = (const float*)d_in[4];
    float* out = (float*)d_out;

    void* pA = nullptr; void* pB = nullptr;
    cudaGetSymbolAddress(&pA, g_A);
    cudaGetSymbolAddress(&pB, g_B);

    EncodeFn enc = nullptr;
    cudaDriverEntryPointQueryResult qres;
    cudaGetDriverEntryPoint("cuTensorMapEncodeTiled", (void**)&enc, cudaEnableDefault, &qres);

    CUtensorMap mapA, mapB;
    encode_map(enc, &mapA, pA, M_TOTAL, 128);
    encode_map(enc, &mapB, pB, N_DIM, 64);

    convert_kernel<<<TOTAL_ROWS / ROWS_PER_BLK, 128>>>(x, gamma, beta, W);

    cudaFuncSetAttribute(gemm_kernel, cudaFuncAttributeMaxDynamicSharedMemorySize, SMEM_DYN);
    dim3 grid(N_DIM / BN, M_TOTAL / BM);   // (32, 196)
    gemm_kernel<<<grid, 128, SMEM_DYN>>>(mapA, mapB, b, out);
}

// round 13
// speedup vs baseline: 1.0255x; 1.0255x over previous
#include <cuda_runtime.h>
#include <cuda.h>
#include <cuda_bf16.h>
#include <math.h>
#include <stdint.h>

#define M_TOTAL 25088   // 128*14*14
#define K_DIM   512
#define N_DIM   2048
#define KX      1024    // interleaved: 16 chunks of [hi(32)|lo(32)]

#define BM 128
#define BN 128
#define STAGES 3
#define NT 16                        // 16 chunks of K=32 (hi+lo together)
#define A_TILE_BYTES (BM * 128)      // 16384
#define B_TILE_BYTES (BN * 128)      // 16384
#define STAGE_BYTES (A_TILE_BYTES + B_TILE_BYTES)  // 32768
#define SMEM_DYN (STAGES * STAGE_BYTES + 1024)

#define TOTAL_ROWS (M_TOTAL + N_DIM) // 27136
#define ROWS_PER_BLK 4               // 4 warps per 128-thread block (convert)

// bf16 hi/lo scratch (allocation-free device globals)
__device__ __nv_bfloat16 g_A[(size_t)M_TOTAL * KX];
__device__ __nv_bfloat16 g_B[(size_t)N_DIM * KX];

// ---------------------------------------------------------------------------
// PTX helpers (sm_90-baseline features only)
// ---------------------------------------------------------------------------
__device__ __forceinline__ uint32_t smem_u32(const void* p) {
    uint32_t a;
    asm("{ .reg .u64 t; cvta.to.shared.u64 t, %1; cvt.u32.u64 %0, t; }" : "=r"(a) : "l"(p));
    return a;
}

#define MBARRIER_INIT(addr, cnt) \
    asm volatile("mbarrier.init.shared.b64 [%0], %1;" :: "r"(addr), "r"(cnt) : "memory")

#define MBARRIER_EXPECT_TX(addr, bytes) \
    asm volatile("mbarrier.arrive.expect_tx.shared.b64 _, [%0], %1;" :: "r"(addr), "r"(bytes) : "memory")

#define MBARRIER_WAIT_PARITY(addr, parity) do {                                   \
    uint32_t _mbar = (uint32_t)(addr);                                            \
    uint32_t _par  = (uint32_t)(parity);                                          \
    uint32_t _done;                                                               \
    asm volatile(                                                                 \
        "{\n\t.reg .pred p;\n\t"                                                  \
        "mbarrier.try_wait.parity.acquire.cta.shared::cta.b64 p, [%1], %2;\n\t"   \
        "selp.b32 %0, 1, 0, p;\n\t}"                                              \
        : "=r"(_done) : "r"(_mbar), "r"(_par) : "memory");                        \
    if (!_done) {                                                                 \
        asm volatile(                                                             \
            "{\n\t.reg .pred P1;\n\t"                                             \
            "WAIT_LOOP_%=:\n\t"                                                   \
            "mbarrier.try_wait.parity.acquire.cta.shared::cta.b64 P1, [%0], %1, 0x989680;\n\t" \
            "@P1 bra.uni WAIT_DONE_%=;\n\t"                                       \
            "bra.uni WAIT_LOOP_%=;\n\t"                                           \
            "WAIT_DONE_%=:\n\t}"                                                  \
            :: "r"(_mbar), "r"(_par) : "memory");                                 \
    }                                                                             \
} while (0)

#define TMA_LOAD_3D(smem_addr, tmap, cx, cy, cz, mbar)                            \
    asm volatile(                                                                 \
        "cp.async.bulk.tensor.3d.shared::cta.global.tile.mbarrier::complete_tx::bytes " \
        "[%0], [%1, {%2, %3, %4}], [%5];"                                         \
        :: "r"((uint32_t)(smem_addr)), "l"(tmap), "r"((int32_t)(cx)),             \
           "r"((int32_t)(cy)), "r"((int32_t)(cz)), "r"((uint32_t)(mbar))          \
        : "memory")

#define LDSM_X4(r, addr) \
    asm volatile("ldmatrix.sync.aligned.m8n8.x4.shared.b16 {%0,%1,%2,%3}, [%4];" \
        : "=r"((r)[0]), "=r"((r)[1]), "=r"((r)[2]), "=r"((r)[3]) : "r"(addr))

#define BAR_SYNC(id)   asm volatile("bar.sync %0, 256;"   :: "r"(id) : "memory")
#define BAR_ARRIVE(id) asm volatile("bar.arrive %0, 256;" :: "r"(id) : "memory")

__device__ __forceinline__ void mma16816(float* d, const uint32_t* a, const uint32_t* b) {
    asm volatile(
        "mma.sync.aligned.m16n8k16.row.col.f32.bf16.bf16.f32 "
        "{%0,%1,%2,%3}, {%4,%5,%6,%7}, {%8,%9}, {%0,%1,%2,%3};"
        : "+f"(d[0]), "+f"(d[1]), "+f"(d[2]), "+f"(d[3])
        : "r"(a[0]), "r"(a[1]), "r"(a[2]), "r"(a[3]), "r"(b[0]), "r"(b[1]));
}

__device__ __forceinline__ void split_bf16(float v, __nv_bfloat16& hi, __nv_bfloat16& lo) {
    hi = __float2bfloat16(v);
    lo = __float2bfloat16(v - __bfloat162float(hi));
}

// ---------------------------------------------------------------------------
// Kernel 1: warp-per-row convert, barrier-free (R11 winner, unchanged).
// ---------------------------------------------------------------------------
__global__ void __launch_bounds__(128) convert_kernel(
    const float* __restrict__ x,
    const float* __restrict__ gamma,
    const float* __restrict__ beta,
    const float* __restrict__ W)
{
    const int warp = threadIdx.x >> 5;
    const int lane = threadIdx.x & 31;
    const int row  = blockIdx.x * ROWS_PER_BLK + warp;

    if (row < M_TOTAL) {
        const float4* xr = reinterpret_cast<const float4*>(x + (size_t)row * K_DIM);
        float4 v[4];
        #pragma unroll
        for (int p = 0; p < 4; p++)
            v[p] = xr[p * 32 + lane];

        float s = 0.0f, sq = 0.0f;
        #pragma unroll
        for (int p = 0; p < 4; p++) {
            s  += v[p].x + v[p].y + v[p].z + v[p].w;
            sq += fmaf(v[p].x, v[p].x, fmaf(v[p].y, v[p].y,
                  fmaf(v[p].z, v[p].z, v[p].w * v[p].w)));
        }
        #pragma unroll
        for (int o = 16; o > 0; o >>= 1) {
            s  += __shfl_xor_sync(0xffffffff, s,  o);
            sq += __shfl_xor_sync(0xffffffff, sq, o);
        }
        const float mean = s * (1.0f / K_DIM);
        const float var  = sq * (1.0f / K_DIM) - mean * mean;
        const float rstd = rsqrtf(var + 1e-6f);

        const float4* gm = reinterpret_cast<const float4*>(gamma);
        const float4* bt = reinterpret_cast<const float4*>(beta);

        #pragma unroll
        for (int p = 0; p < 4; p++) {
            float4 g  = gm[p * 32 + lane];
            float4 be = bt[p * 32 + lane];
            float xn0 = (v[p].x - mean) * rstd * g.x + be.x;
            float xn1 = (v[p].y - mean) * rstd * g.y + be.y;
            float xn2 = (v[p].z - mean) * rstd * g.z + be.z;
            float xn3 = (v[p].w - mean) * rstd * g.w + be.w;

            __nv_bfloat16 h0, h1, h2, h3, l0, l1, l2, l3;
            split_bf16(xn0, h0, l0); split_bf16(xn1, h1, l1);
            split_bf16(xn2, h2, l2); split_bf16(xn3, h3, l3);

            const int j0 = (p * 32 + lane) * 4;
            const int c  = j0 >> 5;
            const int w  = j0 & 31;
            __nv_bfloat16* base = g_A + (size_t)row * KX + c * 64 + w;
            __nv_bfloat162* hd = reinterpret_cast<__nv_bfloat162*>(base);
            __nv_bfloat162* ld = reinterpret_cast<__nv_bfloat162*>(base + 32);
            hd[0] = __nv_bfloat162(h0, h1); hd[1] = __nv_bfloat162(h2, h3);
            ld[0] = __nv_bfloat162(l0, l1); ld[1] = __nv_bfloat162(l2, l3);
        }
    } else {
        const int wrow = row - M_TOTAL;
        const float4* wr = reinterpret_cast<const float4*>(W + (size_t)wrow * K_DIM);
        #pragma unroll
        for (int p = 0; p < 4; p++) {
            float4 v = wr[p * 32 + lane];
            __nv_bfloat16 h0, h1, h2, h3, l0, l1, l2, l3;
            split_bf16(v.x, h0, l0); split_bf16(v.y, h1, l1);
            split_bf16(v.z, h2, l2); split_bf16(v.w, h3, l3);

            const int j0 = (p * 32 + lane) * 4;
            const int c  = j0 >> 5;
            const int w  = j0 & 31;
            __nv_bfloat16* base = g_B + (size_t)wrow * KX + c * 64 + w;
            __nv_bfloat162* hd = reinterpret_cast<__nv_bfloat162*>(base);
            __nv_bfloat162* ld = reinterpret_cast<__nv_bfloat162*>(base + 32);
            hd[0] = __nv_bfloat162(h0, h1); hd[1] = __nv_bfloat162(h2, h3);
            ld[0] = __nv_bfloat162(l0, l1); ld[1] = __nv_bfloat162(l2, l3);
        }
    }
}

// ---------------------------------------------------------------------------
// Kernel 2: TMA-pipelined HMMA GEMM (3-term split), non-blocking consumer
// release: warps 1-7 bar.arrive and keep issuing MMAs; warp 0 bar.sync+refill.
// Rotating barrier id (1 + kt%3) is race-free: reaching chunk k+3 requires
// mbar[k+3] full, which is only issued after bar id (k%3) phase k released.
// ---------------------------------------------------------------------------
__device__ __forceinline__ void issue_tile_load(
    int kt, int s, uint32_t tiles_base, uint32_t mbar,
    const CUtensorMap* mapA, const CUtensorMap* mapB, int bm, int bn)
{
    const uint32_t a_dst = tiles_base + s * STAGE_BYTES;
    const uint32_t b_dst = a_dst + A_TILE_BYTES;
    MBARRIER_EXPECT_TX(mbar, STAGE_BYTES);
    TMA_LOAD_3D(a_dst, mapA, kt * 64, bm, 0, mbar);
    TMA_LOAD_3D(b_dst, mapB, kt * 64, bn, 0, mbar);
}

__global__ void __launch_bounds__(256, 2) gemm_kernel(
    const __grid_constant__ CUtensorMap tma_a,
    const __grid_constant__ CUtensorMap tma_b,
    const float* __restrict__ bias,
    float* __restrict__ out)
{
    extern __shared__ char dynsmem[];
    __shared__ __align__(8) uint64_t mbar_full[STAGES];

    const int tid  = threadIdx.x;
    const int wid  = tid >> 5;
    const int lane = tid & 31;
    const int bm = blockIdx.y * BM;
    const int bn = blockIdx.x * BN;

    const int wm = (wid >> 2) * 64;   // warp m offset (0 or 64)
    const int wn = (wid & 3) * 32;    // warp n offset (0,32,64,96)

    const uint32_t tiles_base = (smem_u32(dynsmem) + 1023u) & ~1023u;

    if (tid == 0) {
        #pragma unroll
        for (int s = 0; s < STAGES; s++)
            MBARRIER_INIT(smem_u32(&mbar_full[s]), 1);
    }
    __syncthreads();

    if (tid == 0) {
        #pragma unroll
        for (int s = 0; s < STAGES; s++)
            issue_tile_load(s, s, tiles_base, smem_u32(&mbar_full[s]), &tma_a, &tma_b, bm, bn);
    }

    // --- per-lane ldmatrix address components (SW128 swizzle, 128B rows) ---
    const int a_row = wm + ((lane >> 3) & 1) * 8 + (lane & 7);
    const uint32_t a_row_off = (uint32_t)a_row * 128u;
    const uint32_t a_xor = (uint32_t)(a_row & 7) * 16u;
    const uint32_t a_kb = (uint32_t)(lane >> 4) * 16u;
    const int b_row = wn + (lane >> 4) * 8 + (lane & 7);
    const uint32_t b_row_off = (uint32_t)b_row * 128u;
    const uint32_t b_xor = (uint32_t)(b_row & 7) * 16u;
    const uint32_t b_kb = (uint32_t)((lane >> 3) & 1) * 16u;

    float acc[4][4][4];
    #pragma unroll
    for (int i = 0; i < 4; i++)
        #pragma unroll
        for (int j = 0; j < 4; j++)
            #pragma unroll
            for (int q = 0; q < 4; q++) acc[i][j][q] = 0.0f;

    for (int kt = 0; kt < NT; kt++) {
        const int s = kt % STAGES;
        const int par = (kt / STAGES) & 1;
        const int barid = 1 + s;
        MBARRIER_WAIT_PARITY(smem_u32(&mbar_full[s]), par);

        const uint32_t a_base = tiles_base + s * STAGE_BYTES + a_row_off;
        const uint32_t b_base = tiles_base + s * STAGE_BYTES + A_TILE_BYTES + b_row_off;

        // within a 128B row: hi bytes [0,64), lo bytes [64,128); ks picks 32B
        #pragma unroll
        for (int ks = 0; ks < 2; ks++) {
            const uint32_t akh = (uint32_t)ks * 32u + a_kb;          // a_hi
            const uint32_t akl = akh + 64u;                          // a_lo
            const uint32_t bkh = (uint32_t)ks * 32u + b_kb;          // b_hi
            const uint32_t bkl = bkh + 64u;                          // b_lo

            uint32_t ah[4][4], bh[2][4], bl[2][4];
            #pragma unroll
            for (int mt = 0; mt < 4; mt++)
                LDSM_X4(ah[mt], a_base + (uint32_t)mt * 2048u + (akh ^ a_xor));
            #pragma unroll
            for (int np = 0; np < 2; np++) {
                LDSM_X4(bh[np], b_base + (uint32_t)np * 2048u + (bkh ^ b_xor));
                LDSM_X4(bl[np], b_base + (uint32_t)np * 2048u + (bkl ^ b_xor));
            }

            if (ks == 1) {
                uint32_t al[4][4];
                #pragma unroll
                for (int mt = 0; mt < 4; mt++)
                    LDSM_X4(al[mt], a_base + (uint32_t)mt * 2048u + (akl ^ a_xor));

                // non-blocking release for warps 1-7; warp 0 syncs + refills
                if (wid == 0) {
                    BAR_SYNC(barid);
                    if (tid == 0 && kt + STAGES < NT)
                        issue_tile_load(kt + STAGES, s, tiles_base,
                                        smem_u32(&mbar_full[s]), &tma_a, &tma_b, bm, bn);
                } else {
                    BAR_ARRIVE(barid);
                }

                #pragma unroll
                for (int mt = 0; mt < 4; mt++)
                    #pragma unroll
                    for (int nt = 0; nt < 4; nt++)
                        mma16816(acc[mt][nt], ah[mt], &bh[nt >> 1][(nt & 1) * 2]);
                #pragma unroll
                for (int mt = 0; mt < 4; mt++)
                    #pragma unroll
                    for (int nt = 0; nt < 4; nt++)
                        mma16816(acc[mt][nt], ah[mt], &bl[nt >> 1][(nt & 1) * 2]);
                #pragma unroll
                for (int mt = 0; mt < 4; mt++)
                    #pragma unroll
                    for (int nt = 0; nt < 4; nt++)
                        mma16816(acc[mt][nt], al[mt], &bh[nt >> 1][(nt & 1) * 2]);
            } else {
                uint32_t al[4][4];
                #pragma unroll
                for (int mt = 0; mt < 4; mt++)
                    LDSM_X4(al[mt], a_base + (uint32_t)mt * 2048u + (akl ^ a_xor));
                #pragma unroll
                for (int mt = 0; mt < 4; mt++)
                    #pragma unroll
                    for (int nt = 0; nt < 4; nt++)
                        mma16816(acc[mt][nt], ah[mt], &bh[nt >> 1][(nt & 1) * 2]);
                #pragma unroll
                for (int mt = 0; mt < 4; mt++)
                    #pragma unroll
                    for (int nt = 0; nt < 4; nt++)
                        mma16816(acc[mt][nt], ah[mt], &bl[nt >> 1][(nt & 1) * 2]);
                #pragma unroll
                for (int mt = 0; mt < 4; mt++)
                    #pragma unroll
                    for (int nt = 0; nt < 4; nt++)
                        mma16816(acc[mt][nt], al[mt], &bh[nt >> 1][(nt & 1) * 2]);
            }
        }
    }

    // --- epilogue: bias + exact GELU, float2 stores ---
    const int gr = lane >> 2;
    const int gc = (lane & 3) * 2;
    #pragma unroll
    for (int nt = 0; nt < 4; nt++) {
        const int n = bn + wn + nt * 8 + gc;
        const float2 b2 = __ldg(reinterpret_cast<const float2*>(bias + n));
        #pragma unroll
        for (int mt = 0; mt < 4; mt++) {
            const int m0 = bm + wm + mt * 16 + gr;
            float v0 = acc[mt][nt][0] + b2.x;
            float v1 = acc[mt][nt][1] + b2.y;
            float v2 = acc[mt][nt][2] + b2.x;
            float v3 = acc[mt][nt][3] + b2.y;
            float2 o0, o1;
            o0.x = 0.5f * v0 * (1.0f + erff(v0 * 0.70710678118654752f));
            o0.y = 0.5f * v1 * (1.0f + erff(v1 * 0.70710678118654752f));
            o1.x = 0.5f * v2 * (1.0f + erff(v2 * 0.70710678118654752f));
            o1.y = 0.5f * v3 * (1.0f + erff(v3 * 0.70710678118654752f));
            *reinterpret_cast<float2*>(out + (size_t)m0 * N_DIM + n) = o0;
            *reinterpret_cast<float2*>(out + (size_t)(m0 + 8) * N_DIM + n) = o1;
        }
    }
}

// ---------------------------------------------------------------------------
// Host side
// ---------------------------------------------------------------------------
typedef CUresult (*EncodeFn)(CUtensorMap*, CUtensorMapDataType, cuuint32_t, void*,
                             const cuuint64_t*, const cuuint64_t*, const cuuint32_t*,
                             const cuuint32_t*, CUtensorMapInterleave, CUtensorMapSwizzle,
                             CUtensorMapL2promotion, CUtensorMapFloatOOBfill);

static void encode_map(EncodeFn enc, CUtensorMap* map, void* base, uint64_t rows) {
    uint64_t dims[3]    = {KX, rows, 1};
    uint64_t strides[2] = {KX * sizeof(__nv_bfloat16), rows * KX * sizeof(__nv_bfloat16)};
    uint32_t box[3]     = {64, 128, 1};
    uint32_t estr[3]    = {1, 1, 1};
    enc(map, CU_TENSOR_MAP_DATA_TYPE_BFLOAT16, 3, base, dims, strides, box, estr,
        CU_TENSOR_MAP_INTERLEAVE_NONE, CU_TENSOR_MAP_SWIZZLE_128B,
        CU_TENSOR_MAP_L2_PROMOTION_L2_128B, CU_TENSOR_MAP_FLOAT_OOB_FILL_NONE);
}

extern "C" void kernel_launch(void* const* d_in, const int* in_sizes, int n_in,
                              void* d_out, int out_size) {
    const float* x     = (const float*)d_in[0];
    const float* gamma = (const float*)d_in[1];
    const float* beta  = (const float*)d_in[2];
    const float* W     = (const float*)d_in[3];
    const float* b     = (const float*)d_in[4];
    float* out = (float*)d_out;

    void* pA = nullptr; void* pB = nullptr;
    cudaGetSymbolAddress(&pA, g_A);
    cudaGetSymbolAddress(&pB, g_B);

    EncodeFn enc = nullptr;
    cudaDriverEntryPointQueryResult qres;
    cudaGetDriverEntryPoint("cuTensorMapEncodeTiled", (void**)&enc, cudaEnableDefault, &qres);

    CUtensorMap mapA, mapB;
    encode_map(enc, &mapA, pA, M_TOTAL);
    encode_map(enc, &mapB, pB, N_DIM);

    convert_kernel<<<TOTAL_ROWS / ROWS_PER_BLK, 128>>>(x, gamma, beta, W);

    cudaFuncSetAttribute(gemm_kernel, cudaFuncAttributeMaxDynamicSharedMemorySize, SMEM_DYN);
    dim3 grid(N_DIM / BN, M_TOTAL / BM);   // (16, 196)
    gemm_kernel<<<grid, 256, SMEM_DYN>>>(mapA, mapB, b, out);
}